// round 1
// baseline (speedup 1.0000x reference)
#include <cuda_runtime.h>
#include <math.h>

#define B_  4
#define S_  1024
#define D_  1024
#define H_  16
#define HD_ 64
#define T_  (B_*S_)       // 4096 tokens
#define E_  8
#define F_  4096
#define NSLOT (T_*2)      // 8192 (token, expert) assignments — always exactly 2T

// ---------------- scratch (device globals; no allocation allowed) ----------------
__device__ float g_xn  [T_*D_];
__device__ float g_qh  [T_*D_];
__device__ float g_kh  [T_*D_];
__device__ float g_vh  [T_*D_];
__device__ float g_attn[T_*D_];
__device__ float g_h   [T_*D_];
__device__ float g_hn  [T_*D_];
__device__ float g_H1  [(size_t)NSLOT*F_];   // also holds G = silu(H1)*H3 in-place
__device__ float g_H3  [(size_t)NSLOT*F_];
__device__ float g_Y   [(size_t)NSLOT*D_];
__device__ int   g_topi[T_*2];
__device__ float g_gate[T_*2];
__device__ int   g_counts[E_];
__device__ int   g_offs[E_];
__device__ int   g_cursor[E_];
__device__ int   g_slot_token[NSLOT];
__device__ int   g_token_slot[T_*2];

// ---------------- packed f32x2 helpers (sm_103a FFMA2) ----------------
__device__ __forceinline__ unsigned long long dup2(float a) {
    unsigned long long d;
    asm("mov.b64 %0, {%1, %1};" : "=l"(d) : "f"(a));
    return d;
}
__device__ __forceinline__ void ffma2(unsigned long long& c, unsigned long long a,
                                      unsigned long long b) {
    asm("fma.rn.f32x2 %0, %1, %2, %0;" : "+l"(c) : "l"(a), "l"(b));
}

// ---------------- misc kernels ----------------
__global__ void zero_counts_kernel() {
    if (threadIdx.x < E_) g_counts[threadIdx.x] = 0;
}

__global__ void __launch_bounds__(256)
rmsnorm_kernel(const float* __restrict__ X, const float* __restrict__ W,
               float* __restrict__ Yo) {
    int t = blockIdx.x, tid = threadIdx.x;
    const float4* xp = (const float4*)(X + (size_t)t * D_);
    float4 x = xp[tid];
    float ss = x.x*x.x + x.y*x.y + x.z*x.z + x.w*x.w;
    __shared__ float red[256];
    red[tid] = ss; __syncthreads();
    for (int s = 128; s > 0; s >>= 1) {
        if (tid < s) red[tid] += red[tid + s];
        __syncthreads();
    }
    float inv = rsqrtf(red[0] * (1.0f / 1024.0f) + 1e-6f);
    float4 w = ((const float4*)W)[tid];
    float4 y;
    y.x = x.x*inv*w.x; y.y = x.y*inv*w.y; y.z = x.z*inv*w.z; y.w = x.w*inv*w.w;
    ((float4*)(Yo + (size_t)t * D_))[tid] = y;
}

// ---------------- generic NT GEMM: C[m,n] = sum_k A[m,k] * B[n,k] ----------------
// MOE: per-expert (blockIdx.z), dynamic row count, optional gather of A rows.
template<bool MOE, bool GATHER, bool ADDRES>
__global__ void __launch_bounds__(256, 2)
gemm_nt(const float* __restrict__ A, const float* __restrict__ Bw,
        float* __restrict__ C, const float* __restrict__ Res,
        int M, int N, int K) {
    int m0b, cnt, base = 0;
    const float* Bptr = Bw;
    if (MOE) {
        int e = blockIdx.z;
        cnt = g_counts[e];
        m0b = blockIdx.y * 128;
        if (m0b >= cnt) return;
        base = g_offs[e];
        Bptr = Bw + (size_t)e * N * K;
    } else {
        cnt = M;
        m0b = blockIdx.y * 128;
    }
    int n0b = blockIdx.x * 128;

    __shared__ float As[16][132];   // transposed: As[k][m]
    __shared__ float Bs[16][132];   // transposed: Bs[k][n]

    int tid = threadIdx.x;
    int tx = tid & 15, ty = tid >> 4;
    int m0 = ty * 8, n0 = tx * 8;

    unsigned long long acc[8][4];
    #pragma unroll
    for (int i = 0; i < 8; i++)
        #pragma unroll
        for (int j = 0; j < 4; j++) acc[i][j] = 0ull;

    int lm[2], ln[2], cc4[2];
    const float* aptr[2];
    const float* bptrs[2];
    #pragma unroll
    for (int r = 0; r < 2; r++) {
        int idx = tid + r * 256;
        int mm = idx >> 2, cc = idx & 3;
        cc4[r] = cc * 4;
        int m = m0b + mm;
        int mg;
        if (MOE) {
            int mc = m < cnt ? m : cnt - 1;
            mg = GATHER ? g_slot_token[base + mc] : (base + mc);
        } else {
            mg = m;
        }
        lm[r] = mm;
        aptr[r] = A + (size_t)mg * K + cc * 4;
        ln[r] = mm;
        bptrs[r] = Bptr + (size_t)(n0b + mm) * K + cc * 4;
    }

    for (int kt = 0; kt < K; kt += 16) {
        #pragma unroll
        for (int r = 0; r < 2; r++) {
            float4 v = *(const float4*)(aptr[r] + kt);
            As[cc4[r]+0][lm[r]] = v.x; As[cc4[r]+1][lm[r]] = v.y;
            As[cc4[r]+2][lm[r]] = v.z; As[cc4[r]+3][lm[r]] = v.w;
            float4 w = *(const float4*)(bptrs[r] + kt);
            Bs[cc4[r]+0][ln[r]] = w.x; Bs[cc4[r]+1][ln[r]] = w.y;
            Bs[cc4[r]+2][ln[r]] = w.z; Bs[cc4[r]+3][ln[r]] = w.w;
        }
        __syncthreads();
        #pragma unroll
        for (int k = 0; k < 16; k++) {
            float4 a0 = *(const float4*)&As[k][m0];
            float4 a1 = *(const float4*)&As[k][m0 + 4];
            unsigned long long b0 = *(const unsigned long long*)&Bs[k][n0];
            unsigned long long b1 = *(const unsigned long long*)&Bs[k][n0 + 2];
            unsigned long long b2 = *(const unsigned long long*)&Bs[k][n0 + 4];
            unsigned long long b3 = *(const unsigned long long*)&Bs[k][n0 + 6];
            float av[8] = {a0.x, a0.y, a0.z, a0.w, a1.x, a1.y, a1.z, a1.w};
            #pragma unroll
            for (int i = 0; i < 8; i++) {
                unsigned long long ad = dup2(av[i]);
                ffma2(acc[i][0], ad, b0);
                ffma2(acc[i][1], ad, b1);
                ffma2(acc[i][2], ad, b2);
                ffma2(acc[i][3], ad, b3);
            }
        }
        __syncthreads();
    }

    #pragma unroll
    for (int i = 0; i < 8; i++) {
        int m = m0b + m0 + i;
        if (!MOE || m < cnt) {
            size_t crow = MOE ? (size_t)(base + m) * N : (size_t)m * N;
            float2* cp = (float2*)(C + crow + n0b + n0);
            #pragma unroll
            for (int j = 0; j < 4; j++) {
                float2 v;
                memcpy(&v, &acc[i][j], 8);
                if (ADDRES) {
                    float2 rr = *(const float2*)(Res + crow + n0b + n0 + j * 2);
                    v.x += rr.x; v.y += rr.y;
                }
                cp[j] = v;
            }
        }
    }
}

// ---------------- RoPE (fold 1/sqrt(HD)=0.125 into Q) ----------------
__global__ void rope_kernel(float* __restrict__ qh, float* __restrict__ kh,
                            const float* __restrict__ cosb,
                            const float* __restrict__ sinb) {
    int idx = blockIdx.x * blockDim.x + threadIdx.x;  // T*H*32
    if (idx >= T_ * H_ * 32) return;
    int p = idx & 31;
    int h = (idx >> 5) & (H_ - 1);
    int t = idx >> 9;
    int s = t & (S_ - 1);
    float c = cosb[s * 32 + p], sn = sinb[s * 32 + p];
    size_t off = (size_t)t * D_ + h * HD_ + 2 * p;
    float2 qv = *(float2*)(qh + off);
    float2 kv = *(float2*)(kh + off);
    float2 qo, ko;
    qo.x = (qv.x * c - qv.y * sn) * 0.125f;
    qo.y = (qv.x * sn + qv.y * c) * 0.125f;
    ko.x = kv.x * c - kv.y * sn;
    ko.y = kv.x * sn + kv.y * c;
    *(float2*)(qh + off) = qo;
    *(float2*)(kh + off) = ko;
}

// ---------------- causal attention: one thread per query row ----------------
__global__ void __launch_bounds__(128)
attn_kernel(const float* __restrict__ Q, const float* __restrict__ Kh,
            const float* __restrict__ Vh, float* __restrict__ O) {
    int b = blockIdx.z, h = blockIdx.y, qt = blockIdx.x;
    int tid = threadIdx.x;
    int r = qt * 128 + tid;  // query position in S
    __shared__ float4 Ks[64][16];
    __shared__ float4 Vs[64][16];
    size_t qbase = ((size_t)(b * S_ + r)) * D_ + h * HD_;
    float4 q4[16];
    #pragma unroll
    for (int i = 0; i < 16; i++) q4[i] = *(const float4*)(Q + qbase + i * 4);
    float4 o4[16];
    #pragma unroll
    for (int i = 0; i < 16; i++) o4[i] = make_float4(0.f, 0.f, 0.f, 0.f);
    float mrow = -1e30f, l = 0.f;

    int ntiles = qt * 2 + 2;
    for (int kt = 0; kt < ntiles; kt++) {
        int k0 = kt * 64;
        int j = tid >> 1, half = (tid & 1) * 8;
        size_t kb = ((size_t)(b * S_ + k0 + j)) * D_ + h * HD_ + half * 4;
        #pragma unroll
        for (int i = 0; i < 8; i++) {
            Ks[j][half + i] = *(const float4*)(Kh + kb + i * 4);
            Vs[j][half + i] = *(const float4*)(Vh + kb + i * 4);
        }
        __syncthreads();
        int jmax = r - k0 + 1;
        if (jmax > 64) jmax = 64;
        for (int jj = 0; jj < jmax; jj++) {
            float s0 = 0.f, s1 = 0.f, s2 = 0.f, s3 = 0.f;
            #pragma unroll
            for (int i = 0; i < 16; i += 4) {
                float4 k0v = Ks[jj][i],   k1v = Ks[jj][i+1];
                float4 k2v = Ks[jj][i+2], k3v = Ks[jj][i+3];
                s0 = fmaf(q4[i].x,   k0v.x, fmaf(q4[i].y,   k0v.y, fmaf(q4[i].z,   k0v.z, fmaf(q4[i].w,   k0v.w, s0))));
                s1 = fmaf(q4[i+1].x, k1v.x, fmaf(q4[i+1].y, k1v.y, fmaf(q4[i+1].z, k1v.z, fmaf(q4[i+1].w, k1v.w, s1))));
                s2 = fmaf(q4[i+2].x, k2v.x, fmaf(q4[i+2].y, k2v.y, fmaf(q4[i+2].z, k2v.z, fmaf(q4[i+2].w, k2v.w, s2))));
                s3 = fmaf(q4[i+3].x, k3v.x, fmaf(q4[i+3].y, k3v.y, fmaf(q4[i+3].z, k3v.z, fmaf(q4[i+3].w, k3v.w, s3))));
            }
            float s = (s0 + s1) + (s2 + s3);
            if (s <= mrow) {                       // fast path: max unchanged
                float p = __expf(s - mrow);
                l += p;
                #pragma unroll
                for (int i = 0; i < 16; i++) {
                    float4 vv = Vs[jj][i];
                    o4[i].x = fmaf(p, vv.x, o4[i].x);
                    o4[i].y = fmaf(p, vv.y, o4[i].y);
                    o4[i].z = fmaf(p, vv.z, o4[i].z);
                    o4[i].w = fmaf(p, vv.w, o4[i].w);
                }
            } else {                               // new max: p = 1
                float esc = __expf(mrow - s);
                mrow = s;
                l = fmaf(l, esc, 1.f);
                #pragma unroll
                for (int i = 0; i < 16; i++) {
                    float4 vv = Vs[jj][i];
                    o4[i].x = fmaf(o4[i].x, esc, vv.x);
                    o4[i].y = fmaf(o4[i].y, esc, vv.y);
                    o4[i].z = fmaf(o4[i].z, esc, vv.z);
                    o4[i].w = fmaf(o4[i].w, esc, vv.w);
                }
            }
        }
        __syncthreads();
    }
    float inv = 1.f / l;
    #pragma unroll
    for (int i = 0; i < 16; i++) {
        float4 o = o4[i];
        o.x *= inv; o.y *= inv; o.z *= inv; o.w *= inv;
        *(float4*)(O + qbase + i * 4) = o;
    }
}

// ---------------- router: logits, top-2, gates ----------------
__global__ void __launch_bounds__(256)
router_kernel(const float* __restrict__ Hn, const float* __restrict__ RW,
              const float* __restrict__ RB) {
    int t = blockIdx.x;
    int w = threadIdx.x >> 5, lane = threadIdx.x & 31;
    const float* x = Hn + (size_t)t * D_;
    const float* rw = RW + (size_t)w * D_;
    float acc = 0.f;
    for (int d = lane * 4; d < D_; d += 128) {
        float4 xv = *(const float4*)(x + d);
        float4 wv = *(const float4*)(rw + d);
        acc += xv.x*wv.x + xv.y*wv.y + xv.z*wv.z + xv.w*wv.w;
    }
    #pragma unroll
    for (int o = 16; o; o >>= 1) acc += __shfl_xor_sync(0xffffffffu, acc, o);
    __shared__ float lg[E_];
    if (lane == 0) lg[w] = acc + RB[w];
    __syncthreads();
    if (threadIdx.x == 0) {
        float v0 = -1e30f, v1 = -1e30f; int i0 = 0, i1 = 0;
        #pragma unroll
        for (int e = 0; e < E_; e++) {
            float v = lg[e];
            if (v > v0) { v1 = v0; i1 = i0; v0 = v; i0 = e; }
            else if (v > v1) { v1 = v; i1 = e; }
        }
        float e1 = expf(v1 - v0);
        float inv = 1.f / (1.f + e1);
        g_topi[t*2] = i0; g_topi[t*2+1] = i1;
        g_gate[t*2] = inv; g_gate[t*2+1] = e1 * inv;
        atomicAdd(&g_counts[i0], 1);
        atomicAdd(&g_counts[i1], 1);
    }
}

__global__ void scan_kernel() {
    if (threadIdx.x == 0) {
        int o = 0;
        for (int e = 0; e < E_; e++) { g_offs[e] = o; g_cursor[e] = o; o += g_counts[e]; }
    }
}

__global__ void assign_kernel() {
    int t = blockIdx.x * blockDim.x + threadIdx.x;
    if (t >= T_) return;
    #pragma unroll
    for (int j = 0; j < 2; j++) {
        int e = g_topi[t*2+j];
        int slot = atomicAdd(&g_cursor[e], 1);
        g_slot_token[slot] = t;
        g_token_slot[t*2+j] = slot;
    }
}

__global__ void swiglu_kernel() {
    size_t i = (size_t)blockIdx.x * blockDim.x + threadIdx.x;  // over NSLOT*F/4
    float4 a = ((const float4*)g_H1)[i];
    float4 c = ((const float4*)g_H3)[i];
    a.x = a.x / (1.f + __expf(-a.x)) * c.x;
    a.y = a.y / (1.f + __expf(-a.y)) * c.y;
    a.z = a.z / (1.f + __expf(-a.z)) * c.z;
    a.w = a.w / (1.f + __expf(-a.w)) * c.w;
    ((float4*)g_H1)[i] = a;   // G in-place
}

__global__ void combine_kernel(const float* __restrict__ Hres, float* __restrict__ Out) {
    int i = blockIdx.x * 256 + threadIdx.x;  // over T*D/4
    int t = i >> 8;
    int d4 = i & 255;
    float g0 = g_gate[t*2], g1 = g_gate[t*2+1];
    int s0 = g_token_slot[t*2], s1 = g_token_slot[t*2+1];
    float4 hv = ((const float4*)(Hres + (size_t)t * D_))[d4];
    float4 y0 = ((const float4*)(g_Y + (size_t)s0 * D_))[d4];
    float4 y1 = ((const float4*)(g_Y + (size_t)s1 * D_))[d4];
    float4 o;
    o.x = hv.x + g0*y0.x + g1*y1.x;
    o.y = hv.y + g0*y0.y + g1*y1.y;
    o.z = hv.z + g0*y0.z + g1*y1.z;
    o.w = hv.w + g0*y0.w + g1*y1.w;
    ((float4*)Out)[i] = o;
}

// ---------------- host ----------------
extern "C" void kernel_launch(void* const* d_in, const int* in_sizes, int n_in,
                              void* d_out, int out_size) {
    const float* q    = (const float*)d_in[0];
    // d_in[1] (k), d_in[2] (v) are unused by the reference (qn passed for all three)
    const float* fcos = (const float*)d_in[3];
    const float* fsin = (const float*)d_in[4];
    const float* attw = (const float*)d_in[5];
    const float* ffnw = (const float*)d_in[6];
    const float* wq   = (const float*)d_in[7];
    const float* wk   = (const float*)d_in[8];
    const float* wv   = (const float*)d_in[9];
    const float* wo   = (const float*)d_in[10];
    const float* rw   = (const float*)d_in[11];
    const float* rb   = (const float*)d_in[12];
    const float* w1   = (const float*)d_in[13];
    const float* w2   = (const float*)d_in[14];
    const float* w3   = (const float*)d_in[15];
    float* out = (float*)d_out;

    float *xn, *qh, *kh, *vh, *attn, *hbuf, *hn, *H1, *H3, *Y;
    cudaGetSymbolAddress((void**)&xn,   g_xn);
    cudaGetSymbolAddress((void**)&qh,   g_qh);
    cudaGetSymbolAddress((void**)&kh,   g_kh);
    cudaGetSymbolAddress((void**)&vh,   g_vh);
    cudaGetSymbolAddress((void**)&attn, g_attn);
    cudaGetSymbolAddress((void**)&hbuf, g_h);
    cudaGetSymbolAddress((void**)&hn,   g_hn);
    cudaGetSymbolAddress((void**)&H1,   g_H1);
    cudaGetSymbolAddress((void**)&H3,   g_H3);
    cudaGetSymbolAddress((void**)&Y,    g_Y);

    zero_counts_kernel<<<1, 32>>>();
    rmsnorm_kernel<<<T_, 256>>>(q, attw, xn);

    dim3 gq(D_ / 128, T_ / 128);
    gemm_nt<false, false, false><<<gq, 256>>>(xn, wq, qh, nullptr, T_, D_, D_);
    gemm_nt<false, false, false><<<gq, 256>>>(xn, wk, kh, nullptr, T_, D_, D_);
    gemm_nt<false, false, false><<<gq, 256>>>(xn, wv, vh, nullptr, T_, D_, D_);

    rope_kernel<<<(T_ * H_ * 32 + 255) / 256, 256>>>(qh, kh, fcos, fsin);
    attn_kernel<<<dim3(S_ / 128, H_, B_), 128>>>(qh, kh, vh, attn);
    gemm_nt<false, false, true><<<gq, 256>>>(attn, wo, hbuf, q, T_, D_, D_);

    rmsnorm_kernel<<<T_, 256>>>(hbuf, ffnw, hn);
    router_kernel<<<T_, 256>>>(hn, rw, rb);
    scan_kernel<<<1, 1>>>();
    assign_kernel<<<T_ / 256, 256>>>();

    gemm_nt<true, true, false><<<dim3(F_ / 128, NSLOT / 128, E_), 256>>>(hn, w1, H1, nullptr, 0, F_, D_);
    gemm_nt<true, true, false><<<dim3(F_ / 128, NSLOT / 128, E_), 256>>>(hn, w3, H3, nullptr, 0, F_, D_);
    swiglu_kernel<<<(int)((size_t)NSLOT * F_ / 4 / 256), 256>>>();
    gemm_nt<true, false, false><<<dim3(D_ / 128, NSLOT / 128, E_), 256>>>(H1, w2, Y, nullptr, 0, D_, F_);

    combine_kernel<<<T_ * D_ / 4 / 256, 256>>>(hbuf, out);
}